// round 3
// baseline (speedup 1.0000x reference)
#include <cuda_runtime.h>
#include <math.h>

#define NPERROW (512*512)            // 262144 elements per (b,c) row
#define NROWS   128                  // B*C
#define NTHREADS 1024
#define NBINS   16384                // top-14-bit histogram
#define BPT     (NBINS/NTHREADS)     // 16 bins per thread
#define GCAP    8192                 // gathered tail buffer capacity per side
#define SCAP    4096                 // candidate sort buffer capacity
#define FULLM   0xFFFFFFFFu

#define SMEM_BYTES ((NBINS + NTHREADS + 2*GCAP + SCAP) * 4)   // 151552

// monotone float -> uint key (ascending key == ascending float)
__device__ __forceinline__ unsigned int f2k(float f) {
    unsigned int u = __float_as_uint(f);
    return u ^ ((unsigned int)((int)u >> 31) | 0x80000000u);
}
__device__ __forceinline__ float k2f(unsigned int k) {
    unsigned int u = (k & 0x80000000u) ? (k ^ 0x80000000u) : ~k;
    return __uint_as_float(u);
}

// warp-aggregated append; ALL 32 lanes of the warp must reach this call
__device__ __forceinline__ void wpush(bool want, unsigned int key,
                                      unsigned int* cnt, unsigned int* buf,
                                      unsigned int cap) {
    unsigned int m = __ballot_sync(FULLM, want);
    if (m == 0u) return;
    int lane = threadIdx.x & 31;
    int leader = __ffs(m) - 1;
    unsigned int base = 0;
    if (lane == leader) base = atomicAdd(cnt, (unsigned int)__popc(m));
    base = __shfl_sync(FULLM, base, leader);
    if (want) {
        unsigned int off = base + (unsigned int)__popc(m & ((1u << lane) - 1u));
        if (off < cap) buf[off] = key;
    }
}

__device__ void bitonic_sort(unsigned int* buf, int m, int tid) {
    int P = 1024;
    while (P < m) P <<= 1;
    for (int i = m + tid; i < P; i += NTHREADS) buf[i] = 0xFFFFFFFFu;
    __syncthreads();
    for (int k = 2; k <= P; k <<= 1) {
        for (int j = k >> 1; j > 0; j >>= 1) {
            for (int i = tid; i < P; i += NTHREADS) {
                int ixj = i ^ j;
                if (ixj > i) {
                    unsigned int a = buf[i], b = buf[ixj];
                    bool up = ((i & k) == 0);
                    if ((a > b) == up) { buf[i] = b; buf[ixj] = a; }
                }
            }
            __syncthreads();
        }
    }
}

extern __shared__ unsigned int smem_u[];

__global__ __launch_bounds__(NTHREADS, 1)
void prox_kernel(const float* __restrict__ x,
                 const float* __restrict__ alpha_p,
                 const float* __restrict__ beta_p,
                 float* __restrict__ out)
{
    unsigned int* hist = smem_u;             // NBINS
    unsigned int* aux  = hist + NBINS;       // NTHREADS
    unsigned int* gLo  = aux + NTHREADS;     // GCAP
    unsigned int* gHi  = gLo + GCAP;         // GCAP
    unsigned int* sbuf = gHi + GCAP;         // SCAP

    __shared__ unsigned int cntLo, cntHi, scnt, midTot;
    __shared__ int          binOf[4];
    __shared__ unsigned int preOf[4];
    __shared__ float        s_v[4];
    __shared__ float        s_scale, s_t;

    const int tid = threadIdx.x;
    const int row = blockIdx.x;
    const float4* xr   = (const float4*)(x   + (size_t)row * NPERROW);
    float4*       outr = (float4*)      (out + (size_t)row * NPERROW);
    const int NV4 = NPERROW / 4;  // 65536 (multiple of NTHREADS -> uniform trip counts)

    // filter cuts (monotone-key bin boundaries)
    const unsigned int BL1 = f2k(-1.0f) >> 18;   // bins <= BL1  -> histogrammed (x <~ -1)
    const unsigned int BH1 = f2k( 1.0f) >> 18;   // bins >= BH1  -> histogrammed (x >~ 1)
    const unsigned int BL2 = f2k(-2.0f) >> 18;   // bins <= BL2  -> gathered low tail
    const unsigned int BH2 = f2k( 2.0f) >> 18;   // bins >= BH2  -> gathered high tail

    // ---- init ----
    #pragma unroll
    for (int j = 0; j < BPT; j++) hist[tid + j * NTHREADS] = 0u;
    if (tid == 0) { cntLo = 0u; cntHi = 0u; midTot = 0u; }
    __syncthreads();

    // ---- Phase A: filtered histogram + fused tail gather (single read pass) ----
    unsigned int mid = 0;
    for (int i = tid; i < NV4; i += NTHREADS) {
        float4 v = xr[i];
        unsigned int ks[4] = {f2k(v.x), f2k(v.y), f2k(v.z), f2k(v.w)};
        #pragma unroll
        for (int e = 0; e < 4; e++) {
            unsigned int b = ks[e] >> 18;
            if (b <= BL1 || b >= BH1) atomicAdd(&hist[b], 1u);
            else                      mid++;
            wpush(b <= BL2, ks[e], &cntLo, gLo, GCAP);
            wpush(b >= BH2, ks[e], &cntHi, gHi, GCAP);
        }
    }
    // reduce middle count (warp reduce + one atomic per warp)
    #pragma unroll
    for (int off = 16; off > 0; off >>= 1) mid += __shfl_down_sync(FULLM, mid, off);
    if ((tid & 31) == 0) atomicAdd(&midTot, mid);
    __syncthreads();
    if (tid == 0) hist[BL1 + 1] += midTot;   // lump middle mass into first middle bin
    __syncthreads();

    // ---- Phase B: scan + locate candidate bins (with exactness fallback) ----
    const unsigned int RANKS[4] = {2621u, 2622u, 259521u, 259522u};
    int mode = 0;   // 0 = filtered hist, 1 = full hist (fallback)
    for (;;) {
        // exclusive prefix over hist
        unsigned int loc[BPT];
        unsigned int s = 0;
        #pragma unroll
        for (int j = 0; j < BPT; j++) { loc[j] = hist[tid * BPT + j]; s += loc[j]; }
        aux[tid] = s;
        __syncthreads();
        for (int off = 1; off < NTHREADS; off <<= 1) {
            unsigned int v   = aux[tid];
            unsigned int add = (tid >= off) ? aux[tid - off] : 0u;
            __syncthreads();
            aux[tid] = v + add;
            __syncthreads();
        }
        unsigned int run = aux[tid] - s;
        #pragma unroll
        for (int j = 0; j < BPT; j++) {
            unsigned int c = loc[j];
            hist[tid * BPT + j] = run;
            run += c;
        }
        __syncthreads();   // neighbors read hist[b+1] below

        #pragma unroll
        for (int j = 0; j < BPT; j++) {
            int b = tid * BPT + j;
            unsigned int p  = hist[b];
            unsigned int nx = (b == NBINS - 1) ? (unsigned int)NPERROW : hist[b + 1];
            #pragma unroll
            for (int q = 0; q < 4; q++) {
                if (p <= RANKS[q] && RANKS[q] < nx) { binOf[q] = b; preOf[q] = p; }
            }
        }
        __syncthreads();

        bool bad = false;
        if (mode == 0) {
            #pragma unroll
            for (int q = 0; q < 4; q++) {
                int b = binOf[q];
                if (b > (int)BL1 && b < (int)BH1) bad = true;  // rank in un-histogrammed middle
            }
        }
        if (!bad) break;

        // fallback: full histogram (exact for any input)
        mode = 1;
        __syncthreads();
        #pragma unroll
        for (int j = 0; j < BPT; j++) hist[tid + j * NTHREADS] = 0u;
        __syncthreads();
        for (int i = tid; i < NV4; i += NTHREADS) {
            float4 v = xr[i];
            atomicAdd(&hist[f2k(v.x) >> 18], 1u);
            atomicAdd(&hist[f2k(v.y) >> 18], 1u);
            atomicAdd(&hist[f2k(v.z) >> 18], 1u);
            atomicAdd(&hist[f2k(v.w) >> 18], 1u);
        }
        __syncthreads();
    }

    // ---- Phase C/D: per side, extract candidates (smem fast path) and sort ----
    #pragma unroll
    for (int side = 0; side < 2; side++) {
        const int b0 = binOf[side * 2];
        const int b1 = binOf[side * 2 + 1];
        const unsigned int kmin = (unsigned int)b0 << 18;
        const unsigned int kmax = (((unsigned int)b1 + 1u) << 18) - 1u;  // wraps to 0xFFFFFFFF at top bin

        if (tid == 0) scnt = 0u;
        __syncthreads();

        const bool fast = (mode == 0) &&
            (side == 0 ? (b1 <= (int)BL2 && cntLo <= GCAP)
                       : (b0 >= (int)BH2 && cntHi <= GCAP));

        if (fast) {
            unsigned int* gb = side ? gHi : gLo;
            unsigned int  gc = side ? cntHi : cntLo;
            // PADDED bound: every lane executes the same number of ballot
            // collectives; out-of-range lanes contribute want=false.
            unsigned int gcr = (gc + NTHREADS - 1u) / NTHREADS * NTHREADS;
            for (unsigned int i = tid; i < gcr; i += NTHREADS) {
                bool inb = (i < gc);
                unsigned int k = inb ? gb[i] : 0u;
                wpush(inb && k >= kmin && k <= kmax, k, &scnt, sbuf, SCAP);
            }
        } else {
            // slow path: re-read row, filter by key range (uniform trip count)
            for (int i = tid; i < NV4; i += NTHREADS) {
                float4 v = xr[i];
                unsigned int ks[4] = {f2k(v.x), f2k(v.y), f2k(v.z), f2k(v.w)};
                #pragma unroll
                for (int e = 0; e < 4; e++)
                    wpush(ks[e] >= kmin && ks[e] <= kmax, ks[e], &scnt, sbuf, SCAP);
            }
        }
        __syncthreads();

        int m = (int)min(scnt, (unsigned int)SCAP);
        bitonic_sort(sbuf, m, tid);
        __syncthreads();

        if (tid == 0) {
            unsigned int r = RANKS[side * 2] - preOf[side * 2];
            s_v[side * 2]     = k2f(sbuf[r]);
            s_v[side * 2 + 1] = k2f(sbuf[r + 1]);
        }
        __syncthreads();
    }

    // ---- threshold ----
    if (tid == 0) {
        double posLo  = 0.01 * (double)(NPERROW - 1);
        double posHi  = 0.99 * (double)(NPERROW - 1);
        double fracLo = posLo - (double)RANKS[0];
        double fracHi = posHi - (double)RANKS[2];

        double i1  = (double)s_v[0] + fracLo * ((double)s_v[1] - (double)s_v[0]);
        double i99 = (double)s_v[2] + fracHi * ((double)s_v[3] - (double)s_v[2]);

        float alpha = alpha_p[0];
        float beta  = beta_p[0];
        float th = (float)(i1 + (i99 - i1) * (double)alpha);
        float mask   = (th > 1e-14f) ? 1.0f : 0.0f;
        float th_new = th * mask + (1.0f - mask);
        s_scale = beta / th_new;
        s_t     = th * mask;
    }
    __syncthreads();

    // ---- Phase E: apply gate ----
    const float scale = s_scale;
    const float t     = s_t;
    for (int i = tid; i < NV4; i += NTHREADS) {
        float4 v = xr[i];
        float4 o;
        o.x = fmaxf(v.x, 0.0f) * (1.0f / (1.0f + __expf(-(scale * (fabsf(v.x) - t)))));
        o.y = fmaxf(v.y, 0.0f) * (1.0f / (1.0f + __expf(-(scale * (fabsf(v.y) - t)))));
        o.z = fmaxf(v.z, 0.0f) * (1.0f / (1.0f + __expf(-(scale * (fabsf(v.z) - t)))));
        o.w = fmaxf(v.w, 0.0f) * (1.0f / (1.0f + __expf(-(scale * (fabsf(v.w) - t)))));
        __stcs(&outr[i], o);
    }
}

extern "C" void kernel_launch(void* const* d_in, const int* in_sizes, int n_in,
                              void* d_out, int out_size)
{
    const float* x     = (const float*)d_in[0];
    const float* alpha = (const float*)d_in[1];
    const float* beta  = (const float*)d_in[2];
    float* out = (float*)d_out;

    cudaFuncSetAttribute(prox_kernel, cudaFuncAttributeMaxDynamicSharedMemorySize, SMEM_BYTES);
    prox_kernel<<<NROWS, NTHREADS, SMEM_BYTES>>>(x, alpha, beta, out);
}

// round 4
// speedup vs baseline: 1.4295x; 1.4295x over previous
#include <cuda_runtime.h>
#include <math.h>

#define NPERROW (512*512)            // 262144 elements per (b,c) row
#define NROWS   128                  // B*C
#define NTHREADS 1024
#define NV4     (NPERROW/4)          // 65536, multiple of NTHREADS
#define NBINS   16384                // top-14-bit histogram
#define BPT     (NBINS/NTHREADS)     // 16
#define MCAP    16384                // mixed tail buffer capacity
#define SCAP    4096                 // candidate sort buffer
#define FULLM   0xFFFFFFFFu

#define SMEM_WORDS (NBINS + NTHREADS + MCAP + SCAP)   // 37888
#define SMEM_BYTES (SMEM_WORDS * 4)                   // 151552

// monotone float -> uint key
__device__ __forceinline__ unsigned int f2k(float f) {
    unsigned int u = __float_as_uint(f);
    return u ^ ((unsigned int)((int)u >> 31) | 0x80000000u);
}
__device__ __forceinline__ float k2f(unsigned int k) {
    unsigned int u = (k & 0x80000000u) ? (k ^ 0x80000000u) : ~k;
    return __uint_as_float(u);
}

// warp-aggregated append; ALL 32 lanes must reach this call
__device__ __forceinline__ void wpush(bool want, unsigned int key,
                                      unsigned int* cnt, unsigned int* buf,
                                      unsigned int cap) {
    unsigned int m = __ballot_sync(FULLM, want);
    if (m == 0u) return;
    int lane = threadIdx.x & 31;
    int leader = __ffs(m) - 1;
    unsigned int base = 0;
    if (lane == leader) base = atomicAdd(cnt, (unsigned int)__popc(m));
    base = __shfl_sync(FULLM, base, leader);
    if (want) {
        unsigned int off = base + (unsigned int)__popc(m & ((1u << lane) - 1u));
        if (off < cap) buf[off] = key;
    }
}

__device__ void bitonic_sort(unsigned int* buf, int m, int tid) {
    int P = 1024;
    while (P < m) P <<= 1;
    for (int i = m + tid; i < P; i += NTHREADS) buf[i] = 0xFFFFFFFFu;
    __syncthreads();
    for (int k = 2; k <= P; k <<= 1) {
        for (int j = k >> 1; j > 0; j >>= 1) {
            for (int i = tid; i < P; i += NTHREADS) {
                int ixj = i ^ j;
                if (ixj > i) {
                    unsigned int a = buf[i], b = buf[ixj];
                    bool up = ((i & k) == 0);
                    if ((a > b) == up) { buf[i] = b; buf[ixj] = a; }
                }
            }
            __syncthreads();
        }
    }
}

extern __shared__ unsigned int smem_u[];

__global__ __launch_bounds__(NTHREADS, 1)
void prox_kernel(const float* __restrict__ x,
                 const float* __restrict__ alpha_p,
                 const float* __restrict__ beta_p,
                 float* __restrict__ out)
{
    unsigned int* hist = smem_u;             // NBINS
    unsigned int* aux  = hist + NBINS;       // NTHREADS
    unsigned int* mix  = aux + NTHREADS;     // MCAP
    unsigned int* sbuf = mix + MCAP;         // SCAP

    __shared__ unsigned int mcnt, loTot, scnt;
    __shared__ int          binOf[4];
    __shared__ unsigned int preOf[4];
    __shared__ float        s_v[4];
    __shared__ float        s_scale, s_t;

    const int tid  = threadIdx.x;
    const int lane = tid & 31;
    const int row  = blockIdx.x;
    const float4* xr   = (const float4*)(x   + (size_t)row * NPERROW);
    float4*       outr = (float4*)      (out + (size_t)row * NPERROW);

    if (tid == 0) { mcnt = 0u; loTot = 0u; }
    __syncthreads();

    // ================= Phase A: gather |x|>2 into mixed buffer =================
    // Per float4: 4 compares, one 5-step warp scan, one amortized atomic.
    unsigned int cLo = 0;
    #pragma unroll 2
    for (int i = tid; i < NV4; i += NTHREADS) {
        float4 v = xr[i];
        bool w0 = fabsf(v.x) > 2.0f;
        bool w1 = fabsf(v.y) > 2.0f;
        bool w2 = fabsf(v.z) > 2.0f;
        bool w3 = fabsf(v.w) > 2.0f;
        cLo += (v.x < -2.0f) + (v.y < -2.0f) + (v.z < -2.0f) + (v.w < -2.0f);
        int nw = (int)w0 + (int)w1 + (int)w2 + (int)w3;

        // warp inclusive scan of nw
        int pre = nw;
        #pragma unroll
        for (int o = 1; o < 32; o <<= 1) {
            int t = __shfl_up_sync(FULLM, pre, o);
            if (lane >= o) pre += t;
        }
        int tot = __shfl_sync(FULLM, pre, 31);
        if (tot) {
            unsigned int base = 0;
            if (lane == 31) base = atomicAdd(&mcnt, (unsigned int)tot);
            base = __shfl_sync(FULLM, base, 31);
            unsigned int off = base + (unsigned int)(pre - nw);
            if (w0) { if (off < MCAP) mix[off] = f2k(v.x); off++; }
            if (w1) { if (off < MCAP) mix[off] = f2k(v.y); off++; }
            if (w2) { if (off < MCAP) mix[off] = f2k(v.z); off++; }
            if (w3) { if (off < MCAP) mix[off] = f2k(v.w); off++; }
        }
    }
    // block-reduce low-tail count
    #pragma unroll
    for (int o = 16; o > 0; o >>= 1) cLo += __shfl_down_sync(FULLM, cLo, o);
    if (lane == 0) atomicAdd(&loTot, cLo);
    __syncthreads();

    const unsigned int M      = mcnt;
    const unsigned int cntLo  = loTot;
    const unsigned int cntHi  = (M >= cntLo) ? (M - cntLo) : 0u;
    const bool fastOK = (M <= MCAP) && (cntLo >= 2623u) && (cntHi >= 2623u);

    // ================= Phase B: histogram (mixed set OR full row) =================
    #pragma unroll
    for (int j = 0; j < BPT; j++) hist[tid + j * NTHREADS] = 0u;
    __syncthreads();

    if (fastOK) {
        for (unsigned int i = tid; i < M; i += NTHREADS)
            atomicAdd(&hist[mix[i] >> 18], 1u);
    } else {
        // exact fallback: full-row histogram
        for (int i = tid; i < NV4; i += NTHREADS) {
            float4 v = xr[i];
            atomicAdd(&hist[f2k(v.x) >> 18], 1u);
            atomicAdd(&hist[f2k(v.y) >> 18], 1u);
            atomicAdd(&hist[f2k(v.z) >> 18], 1u);
            atomicAdd(&hist[f2k(v.w) >> 18], 1u);
        }
    }
    __syncthreads();

    const unsigned int TOT = fastOK ? M : (unsigned int)NPERROW;
    unsigned int RANKS[4];
    if (fastOK) {
        RANKS[0] = 2621u; RANKS[1] = 2622u; RANKS[2] = M - 2623u; RANKS[3] = M - 2622u;
    } else {
        RANKS[0] = 2621u; RANKS[1] = 2622u; RANKS[2] = 259521u;   RANKS[3] = 259522u;
    }

    // exclusive prefix over hist
    {
        unsigned int loc[BPT];
        unsigned int s = 0;
        #pragma unroll
        for (int j = 0; j < BPT; j++) { loc[j] = hist[tid * BPT + j]; s += loc[j]; }
        aux[tid] = s;
        __syncthreads();
        for (int off = 1; off < NTHREADS; off <<= 1) {
            unsigned int v   = aux[tid];
            unsigned int add = (tid >= off) ? aux[tid - off] : 0u;
            __syncthreads();
            aux[tid] = v + add;
            __syncthreads();
        }
        unsigned int run = aux[tid] - s;
        #pragma unroll
        for (int j = 0; j < BPT; j++) {
            unsigned int c = loc[j];
            hist[tid * BPT + j] = run;
            run += c;
        }
    }
    __syncthreads();   // neighbors read hist[b+1] below

    #pragma unroll
    for (int j = 0; j < BPT; j++) {
        int b = tid * BPT + j;
        unsigned int p  = hist[b];
        unsigned int nx = (b == NBINS - 1) ? TOT : hist[b + 1];
        #pragma unroll
        for (int q = 0; q < 4; q++) {
            if (p <= RANKS[q] && RANKS[q] < nx) { binOf[q] = b; preOf[q] = p; }
        }
    }
    __syncthreads();

    // ============ Phase C/D: extract candidates per side, sort, pick ============
    #pragma unroll
    for (int side = 0; side < 2; side++) {
        const int b0 = binOf[side * 2];
        const int b1 = binOf[side * 2 + 1];
        const unsigned int kmin = (unsigned int)b0 << 18;
        const unsigned int kmax = (((unsigned int)(b1 + 1)) << 18) - 1u;  // wraps at top bin

        if (tid == 0) scnt = 0u;
        __syncthreads();

        if (fastOK) {
            // uniform trip count: padded bound, all lanes hit every ballot
            unsigned int Mr = (M + NTHREADS - 1u) / NTHREADS * NTHREADS;
            for (unsigned int i = tid; i < Mr; i += NTHREADS) {
                bool inb = (i < M);
                unsigned int k = inb ? mix[i] : 0u;
                wpush(inb && k >= kmin && k <= kmax, k, &scnt, sbuf, SCAP);
            }
        } else {
            for (int i = tid; i < NV4; i += NTHREADS) {
                float4 v = xr[i];
                unsigned int ks[4] = {f2k(v.x), f2k(v.y), f2k(v.z), f2k(v.w)};
                #pragma unroll
                for (int e = 0; e < 4; e++)
                    wpush(ks[e] >= kmin && ks[e] <= kmax, ks[e], &scnt, sbuf, SCAP);
            }
        }
        __syncthreads();

        int m = (int)min(scnt, (unsigned int)SCAP);
        bitonic_sort(sbuf, m, tid);
        __syncthreads();

        if (tid == 0) {
            unsigned int r = RANKS[side * 2] - preOf[side * 2];
            if ((int)r > m - 2) r = (unsigned int)(m - 2);   // safety clamp
            s_v[side * 2]     = k2f(sbuf[r]);
            s_v[side * 2 + 1] = k2f(sbuf[r + 1]);
        }
        __syncthreads();
    }

    // ================= threshold =================
    if (tid == 0) {
        double posLo  = 0.01 * (double)(NPERROW - 1);
        double posHi  = 0.99 * (double)(NPERROW - 1);
        double fracLo = posLo - 2621.0;
        double fracHi = posHi - 259521.0;

        double i1  = (double)s_v[0] + fracLo * ((double)s_v[1] - (double)s_v[0]);
        double i99 = (double)s_v[2] + fracHi * ((double)s_v[3] - (double)s_v[2]);

        float alpha = alpha_p[0];
        float beta  = beta_p[0];
        float th = (float)(i1 + (i99 - i1) * (double)alpha);
        float mask   = (th > 1e-14f) ? 1.0f : 0.0f;
        float th_new = th * mask + (1.0f - mask);
        s_scale = beta / th_new;
        s_t     = th * mask;
    }
    __syncthreads();

    // ================= Phase E: apply gate =================
    const float scale = s_scale;
    const float t     = s_t;
    #pragma unroll 2
    for (int i = tid; i < NV4; i += NTHREADS) {
        float4 v = xr[i];
        float4 o;
        o.x = fmaxf(v.x, 0.0f) * __fdividef(1.0f, 1.0f + __expf(-(scale * (fabsf(v.x) - t))));
        o.y = fmaxf(v.y, 0.0f) * __fdividef(1.0f, 1.0f + __expf(-(scale * (fabsf(v.y) - t))));
        o.z = fmaxf(v.z, 0.0f) * __fdividef(1.0f, 1.0f + __expf(-(scale * (fabsf(v.z) - t))));
        o.w = fmaxf(v.w, 0.0f) * __fdividef(1.0f, 1.0f + __expf(-(scale * (fabsf(v.w) - t))));
        __stcs(&outr[i], o);
    }
}

extern "C" void kernel_launch(void* const* d_in, const int* in_sizes, int n_in,
                              void* d_out, int out_size)
{
    const float* x     = (const float*)d_in[0];
    const float* alpha = (const float*)d_in[1];
    const float* beta  = (const float*)d_in[2];
    float* out = (float*)d_out;

    cudaFuncSetAttribute(prox_kernel, cudaFuncAttributeMaxDynamicSharedMemorySize, SMEM_BYTES);
    prox_kernel<<<NROWS, NTHREADS, SMEM_BYTES>>>(x, alpha, beta, out);
}

// round 5
// speedup vs baseline: 1.5658x; 1.0953x over previous
#include <cuda_runtime.h>
#include <math.h>

#define NPERROW (512*512)            // 262144 elements per (b,c) row
#define NROWS   128
#define NTHREADS 1024
#define NV4     (NPERROW/4)          // 65536
#define NBINS   16384                // top-14-bit histogram
#define BPT     (NBINS/NTHREADS)     // 16
#define NWARP   32
#define SEGCAP  512                  // per-warp tail segment (exp ~372 for N(0,1))
#define MCAP    (NWARP*SEGCAP)       // 16384
#define SCAP    4096
#define FULLM   0xFFFFFFFFu

#define SMEM_WORDS (NBINS + NTHREADS + MCAP + SCAP)   // 37888
#define SMEM_BYTES (SMEM_WORDS * 4)

// gate kernel config
#define GTHREADS 256
#define CHUNKS_PER_ROW 16
#define GGRID   (NROWS*CHUNKS_PER_ROW)       // 2048
#define V4_PER_CHUNK (NV4/CHUNKS_PER_ROW)    // 4096

__device__ float g_scale[NROWS];
__device__ float g_t[NROWS];

// monotone float -> uint key
__device__ __forceinline__ unsigned int f2k(float f) {
    unsigned int u = __float_as_uint(f);
    return u ^ ((unsigned int)((int)u >> 31) | 0x80000000u);
}
__device__ __forceinline__ float k2f(unsigned int k) {
    unsigned int u = (k & 0x80000000u) ? (k ^ 0x80000000u) : ~k;
    return __uint_as_float(u);
}
__device__ __forceinline__ float ex2a(float x){ float r; asm("ex2.approx.ftz.f32 %0, %1;" : "=f"(r) : "f"(x)); return r; }
__device__ __forceinline__ float rcpa(float x){ float r; asm("rcp.approx.ftz.f32 %0, %1;" : "=f"(r) : "f"(x)); return r; }

// warp-aggregated append; ALL 32 lanes must reach this call
__device__ __forceinline__ void wpush(bool want, unsigned int key,
                                      unsigned int* cnt, unsigned int* buf,
                                      unsigned int cap) {
    unsigned int m = __ballot_sync(FULLM, want);
    if (m == 0u) return;
    int lane = threadIdx.x & 31;
    int leader = __ffs(m) - 1;
    unsigned int base = 0;
    if (lane == leader) base = atomicAdd(cnt, (unsigned int)__popc(m));
    base = __shfl_sync(FULLM, base, leader);
    if (want) {
        unsigned int off = base + (unsigned int)__popc(m & ((1u << lane) - 1u));
        if (off < cap) buf[off] = key;
    }
}

__device__ void bitonic_sort(unsigned int* buf, int m, int tid) {
    int P = 1024;
    while (P < m) P <<= 1;
    for (int i = m + tid; i < P; i += NTHREADS) buf[i] = 0xFFFFFFFFu;
    __syncthreads();
    for (int k = 2; k <= P; k <<= 1) {
        for (int j = k >> 1; j > 0; j >>= 1) {
            for (int i = tid; i < P; i += NTHREADS) {
                int ixj = i ^ j;
                if (ixj > i) {
                    unsigned int a = buf[i], b = buf[ixj];
                    bool up = ((i & k) == 0);
                    if ((a > b) == up) { buf[i] = b; buf[ixj] = a; }
                }
            }
            __syncthreads();
        }
    }
}

extern __shared__ unsigned int smem_u[];

// ===================== Kernel 1: per-row threshold =====================
__global__ __launch_bounds__(NTHREADS, 1)
void thresh_kernel(const float* __restrict__ x,
                   const float* __restrict__ alpha_p,
                   const float* __restrict__ beta_p)
{
    unsigned int* hist = smem_u;             // NBINS
    unsigned int* aux  = hist + NBINS;       // NTHREADS
    unsigned int* mix  = aux + NTHREADS;     // MCAP (32 x SEGCAP)
    unsigned int* sbuf = mix + MCAP;         // SCAP

    __shared__ unsigned int wcnt[NWARP];
    __shared__ unsigned int s_M, scnt;
    __shared__ int          s_szok;
    __shared__ int          binOf[4];
    __shared__ unsigned int preOf[4];
    __shared__ float        s_v[4];

    const int tid  = threadIdx.x;
    const int lane = tid & 31;
    const int wid  = tid >> 5;
    const int row  = blockIdx.x;
    const float4* xr = (const float4*)(x + (size_t)row * NPERROW);

    const unsigned int BL2 = f2k(-2.0f) >> 18;   // 4095
    const unsigned int BH2 = f2k( 2.0f) >> 18;   // 12288

    // ---- Phase A: per-warp register-counter compaction of |x|>2 ----
    unsigned int wbase = 0;
    unsigned int* seg = mix + wid * SEGCAP;
    const unsigned int lt = (1u << lane) - 1u;

    #pragma unroll 4
    for (int i = tid; i < NV4; i += NTHREADS) {
        float4 v = xr[i];
        bool w0 = fabsf(v.x) > 2.0f;
        bool w1 = fabsf(v.y) > 2.0f;
        bool w2 = fabsf(v.z) > 2.0f;
        bool w3 = fabsf(v.w) > 2.0f;
        unsigned int m0 = __ballot_sync(FULLM, w0);
        unsigned int m1 = __ballot_sync(FULLM, w1);
        unsigned int m2 = __ballot_sync(FULLM, w2);
        unsigned int m3 = __ballot_sync(FULLM, w3);
        unsigned int t0 = __popc(m0), t1 = __popc(m1), t2 = __popc(m2);
        unsigned int tot = t0 + t1 + t2 + __popc(m3);
        if (tot) {
            if (w0) { unsigned int o = wbase + __popc(m0 & lt);                 if (o < SEGCAP) seg[o] = f2k(v.x); }
            if (w1) { unsigned int o = wbase + t0 + __popc(m1 & lt);            if (o < SEGCAP) seg[o] = f2k(v.y); }
            if (w2) { unsigned int o = wbase + t0 + t1 + __popc(m2 & lt);      if (o < SEGCAP) seg[o] = f2k(v.z); }
            if (w3) { unsigned int o = wbase + t0 + t1 + t2 + __popc(m3 & lt); if (o < SEGCAP) seg[o] = f2k(v.w); }
            wbase += tot;
        }
    }
    if (lane == 0) wcnt[wid] = wbase;
    __syncthreads();

    if (tid == 0) {
        unsigned int m = 0; int ok = 1;
        #pragma unroll
        for (int w = 0; w < NWARP; w++) {
            if (wcnt[w] > SEGCAP) ok = 0;
            m += wcnt[w];
        }
        if (m < 5246u) ok = 0;   // both tails must hold >= 2623 combined minimum
        s_M = m; s_szok = ok;
    }
    __syncthreads();

    const unsigned int M = s_M;
    int mode = s_szok ? 0 : 1;   // 0 = fast (tail set), 1 = exact full fallback

    unsigned int RANKS[4];
    unsigned int TOT;

    for (;;) {
        // zero hist
        #pragma unroll
        for (int j = 0; j < BPT; j++) hist[tid + j * NTHREADS] = 0u;
        __syncthreads();

        if (mode == 0) {
            TOT = M;
            RANKS[0] = 2621u; RANKS[1] = 2622u; RANKS[2] = M - 2623u; RANKS[3] = M - 2622u;
            for (int i = tid; i < MCAP; i += NTHREADS) {
                int w = i >> 9, p = i & (SEGCAP - 1);
                if (p < (int)wcnt[w]) atomicAdd(&hist[mix[i] >> 18], 1u);
            }
        } else {
            TOT = (unsigned int)NPERROW;
            RANKS[0] = 2621u; RANKS[1] = 2622u; RANKS[2] = 259521u; RANKS[3] = 259522u;
            for (int i = tid; i < NV4; i += NTHREADS) {
                float4 v = xr[i];
                atomicAdd(&hist[f2k(v.x) >> 18], 1u);
                atomicAdd(&hist[f2k(v.y) >> 18], 1u);
                atomicAdd(&hist[f2k(v.z) >> 18], 1u);
                atomicAdd(&hist[f2k(v.w) >> 18], 1u);
            }
        }
        __syncthreads();

        // exclusive prefix over hist
        {
            unsigned int loc[BPT];
            unsigned int s = 0;
            #pragma unroll
            for (int j = 0; j < BPT; j++) { loc[j] = hist[tid * BPT + j]; s += loc[j]; }
            aux[tid] = s;
            __syncthreads();
            for (int off = 1; off < NTHREADS; off <<= 1) {
                unsigned int v   = aux[tid];
                unsigned int add = (tid >= off) ? aux[tid - off] : 0u;
                __syncthreads();
                aux[tid] = v + add;
                __syncthreads();
            }
            unsigned int run = aux[tid] - s;
            #pragma unroll
            for (int j = 0; j < BPT; j++) {
                unsigned int c = loc[j];
                hist[tid * BPT + j] = run;
                run += c;
            }
        }
        __syncthreads();   // neighbors read hist[b+1] below

        #pragma unroll
        for (int j = 0; j < BPT; j++) {
            int b = tid * BPT + j;
            unsigned int p  = hist[b];
            unsigned int nx = (b == NBINS - 1) ? TOT : hist[b + 1];
            #pragma unroll
            for (int q = 0; q < 4; q++) {
                if (p <= RANKS[q] && RANKS[q] < nx) { binOf[q] = b; preOf[q] = p; }
            }
        }
        __syncthreads();

        if (mode == 0) {
            // quantile ranks must lie strictly inside the gathered tails
            bool bad = (binOf[1] > (int)BL2) || (binOf[2] < (int)BH2);
            if (bad) { mode = 1; __syncthreads(); continue; }
        }
        break;
    }

    // ---- extract candidates per side, sort, pick order stats ----
    #pragma unroll
    for (int side = 0; side < 2; side++) {
        const int b0 = binOf[side * 2];
        const int b1 = binOf[side * 2 + 1];
        const unsigned int kmin = (unsigned int)b0 << 18;
        const unsigned int kmax = (((unsigned int)(b1 + 1)) << 18) - 1u;

        if (tid == 0) scnt = 0u;
        __syncthreads();

        if (mode == 0) {
            // MCAP multiple of NTHREADS -> uniform ballot trip counts
            for (int i = tid; i < MCAP; i += NTHREADS) {
                int w = i >> 9, p = i & (SEGCAP - 1);
                bool inb = p < (int)wcnt[w];
                unsigned int k = inb ? mix[i] : 0u;
                wpush(inb && k >= kmin && k <= kmax, k, &scnt, sbuf, SCAP);
            }
        } else {
            for (int i = tid; i < NV4; i += NTHREADS) {
                float4 v = xr[i];
                unsigned int ks[4] = {f2k(v.x), f2k(v.y), f2k(v.z), f2k(v.w)};
                #pragma unroll
                for (int e = 0; e < 4; e++)
                    wpush(ks[e] >= kmin && ks[e] <= kmax, ks[e], &scnt, sbuf, SCAP);
            }
        }
        __syncthreads();

        int m = (int)min(scnt, (unsigned int)SCAP);
        bitonic_sort(sbuf, m, tid);
        __syncthreads();

        if (tid == 0) {
            unsigned int r = RANKS[side * 2] - preOf[side * 2];
            if ((int)r > m - 2) r = (unsigned int)(m - 2);
            s_v[side * 2]     = k2f(sbuf[r]);
            s_v[side * 2 + 1] = k2f(sbuf[r + 1]);
        }
        __syncthreads();
    }

    if (tid == 0) {
        double posLo  = 0.01 * (double)(NPERROW - 1);
        double posHi  = 0.99 * (double)(NPERROW - 1);
        double fracLo = posLo - 2621.0;
        double fracHi = posHi - 259521.0;

        double i1  = (double)s_v[0] + fracLo * ((double)s_v[1] - (double)s_v[0]);
        double i99 = (double)s_v[2] + fracHi * ((double)s_v[3] - (double)s_v[2]);

        float alpha = alpha_p[0];
        float beta  = beta_p[0];
        float th = (float)(i1 + (i99 - i1) * (double)alpha);
        float mask   = (th > 1e-14f) ? 1.0f : 0.0f;
        float th_new = th * mask + (1.0f - mask);
        g_scale[row] = beta / th_new;
        g_t[row]     = th * mask;
    }
}

// ===================== Kernel 2: streaming gate =====================
__global__ __launch_bounds__(GTHREADS)
void gate_kernel(const float* __restrict__ x, float* __restrict__ out)
{
    const int c   = blockIdx.x;
    const int row = c >> 4;            // CHUNKS_PER_ROW = 16
    const int chk = c & 15;
    const float4* xr   = (const float4*)(x   + (size_t)row * NPERROW) + (size_t)chk * V4_PER_CHUNK;
    float4*       outr = (float4*)      (out + (size_t)row * NPERROW) + (size_t)chk * V4_PER_CHUNK;

    const float scale = g_scale[row];
    const float t     = g_t[row];
    const float L2E   = 1.4426950408889634f;
    const float a = scale * L2E;        // exp(-(scale*(|x|-t))) = 2^(-a*|x| + b)
    const float b = scale * t * L2E;

    #pragma unroll 4
    for (int i = threadIdx.x; i < V4_PER_CHUNK; i += GTHREADS) {
        float4 v = xr[i];
        float4 o;
        o.x = fmaxf(v.x, 0.0f) * rcpa(1.0f + ex2a(fmaf(fabsf(v.x), -a, b)));
        o.y = fmaxf(v.y, 0.0f) * rcpa(1.0f + ex2a(fmaf(fabsf(v.y), -a, b)));
        o.z = fmaxf(v.z, 0.0f) * rcpa(1.0f + ex2a(fmaf(fabsf(v.z), -a, b)));
        o.w = fmaxf(v.w, 0.0f) * rcpa(1.0f + ex2a(fmaf(fabsf(v.w), -a, b)));
        __stcs(&outr[i], o);
    }
}

extern "C" void kernel_launch(void* const* d_in, const int* in_sizes, int n_in,
                              void* d_out, int out_size)
{
    const float* x     = (const float*)d_in[0];
    const float* alpha = (const float*)d_in[1];
    const float* beta  = (const float*)d_in[2];
    float* out = (float*)d_out;

    cudaFuncSetAttribute(thresh_kernel, cudaFuncAttributeMaxDynamicSharedMemorySize, SMEM_BYTES);
    thresh_kernel<<<NROWS, NTHREADS, SMEM_BYTES>>>(x, alpha, beta);
    gate_kernel<<<GGRID, GTHREADS>>>(x, out);
}

// round 6
// speedup vs baseline: 1.6872x; 1.0775x over previous
#include <cuda_runtime.h>
#include <math.h>

#define NPERROW (512*512)            // 262144
#define NROWS   128
#define NV4     (NPERROW/4)          // 65536
#define FULLM   0xFFFFFFFFu

// ---- gather / gate shape ----
#define CHUNKS  16
#define GTH     256
#define V4C     (NV4/CHUNKS)         // 4096 float4 per chunk
#define V4T     (V4C/GTH)            // 16 float4 per thread
#define GWARPS  (GTH/32)             // 8
#define WSEG    256                  // per-warp smem staging cap (exp ~93, 17 sigma)
#define CSEG    1024                 // per-chunk global segment cap (exp ~746, 10 sigma)

// ---- selection ----
#define NTHREADS 1024
#define NBINS   16384                // top-14-bit histogram
#define BPT     (NBINS/NTHREADS)     // 16
#define MCAP    (CHUNKS*CSEG)        // 16384
#define SCAP    4096
#define SMEM_WORDS (NBINS + NTHREADS + MCAP + SCAP)   // 37888
#define SMEM_BYTES (SMEM_WORDS*4)

__device__ unsigned int g_buf[NROWS][CHUNKS*CSEG];   // 8 MB scratch
__device__ unsigned int g_ccnt[NROWS][CHUNKS];       // per-chunk counts (0xFFFFFFFF = overflow)
__device__ float g_scale[NROWS];
__device__ float g_t[NROWS];

// monotone float -> uint key
__device__ __forceinline__ unsigned int f2k(float f) {
    unsigned int u = __float_as_uint(f);
    return u ^ ((unsigned int)((int)u >> 31) | 0x80000000u);
}
__device__ __forceinline__ float k2f(unsigned int k) {
    unsigned int u = (k & 0x80000000u) ? (k ^ 0x80000000u) : ~k;
    return __uint_as_float(u);
}
__device__ __forceinline__ float ex2a(float x){ float r; asm("ex2.approx.ftz.f32 %0, %1;" : "=f"(r) : "f"(x)); return r; }
__device__ __forceinline__ float rcpa(float x){ float r; asm("rcp.approx.ftz.f32 %0, %1;" : "=f"(r) : "f"(x)); return r; }

// warp-aggregated append; ALL 32 lanes must reach this call
__device__ __forceinline__ void wpush(bool want, unsigned int key,
                                      unsigned int* cnt, unsigned int* buf,
                                      unsigned int cap) {
    unsigned int m = __ballot_sync(FULLM, want);
    if (m == 0u) return;
    int lane = threadIdx.x & 31;
    int leader = __ffs(m) - 1;
    unsigned int base = 0;
    if (lane == leader) base = atomicAdd(cnt, (unsigned int)__popc(m));
    base = __shfl_sync(FULLM, base, leader);
    if (want) {
        unsigned int off = base + (unsigned int)__popc(m & ((1u << lane) - 1u));
        if (off < cap) buf[off] = key;
    }
}

__device__ void bitonic_sort(unsigned int* buf, int m, int tid) {
    int P = 1024;
    while (P < m) P <<= 1;
    for (int i = m + tid; i < P; i += NTHREADS) buf[i] = 0xFFFFFFFFu;
    __syncthreads();
    for (int k = 2; k <= P; k <<= 1) {
        for (int j = k >> 1; j > 0; j >>= 1) {
            for (int i = tid; i < P; i += NTHREADS) {
                int ixj = i ^ j;
                if (ixj > i) {
                    unsigned int a = buf[i], b = buf[ixj];
                    bool up = ((i & k) == 0);
                    if ((a > b) == up) { buf[i] = b; buf[ixj] = a; }
                }
            }
            __syncthreads();
        }
    }
}

// ===================== Kernel 1: wide tail gather =====================
__global__ __launch_bounds__(GTH)
void gather_kernel(const float* __restrict__ x)
{
    __shared__ unsigned int wseg[GWARPS][WSEG];
    __shared__ unsigned int wc[GWARPS];
    __shared__ unsigned int pre[GWARPS];
    __shared__ unsigned int s_tot;

    const int tid  = threadIdx.x;
    const int lane = tid & 31;
    const int wid  = tid >> 5;
    const int row  = blockIdx.x >> 4;
    const int chk  = blockIdx.x & (CHUNKS - 1);
    const float4* xr = (const float4*)(x + (size_t)row * NPERROW) + (size_t)chk * V4C;
    const unsigned int lt = (1u << lane) - 1u;

    unsigned int wbase = 0;
    #pragma unroll 4
    for (int it = 0; it < V4T; it++) {
        float4 v = __ldcs(&xr[tid + it * GTH]);
        bool w0 = fabsf(v.x) > 2.0f;
        bool w1 = fabsf(v.y) > 2.0f;
        bool w2 = fabsf(v.z) > 2.0f;
        bool w3 = fabsf(v.w) > 2.0f;
        unsigned int m0 = __ballot_sync(FULLM, w0);
        unsigned int m1 = __ballot_sync(FULLM, w1);
        unsigned int m2 = __ballot_sync(FULLM, w2);
        unsigned int m3 = __ballot_sync(FULLM, w3);
        unsigned int t0 = __popc(m0), t1 = __popc(m1), t2 = __popc(m2);
        unsigned int tot = t0 + t1 + t2 + __popc(m3);
        if (tot) {
            if (w0) { unsigned int o = wbase + __popc(m0 & lt);                if (o < WSEG) wseg[wid][o] = f2k(v.x); }
            if (w1) { unsigned int o = wbase + t0 + __popc(m1 & lt);           if (o < WSEG) wseg[wid][o] = f2k(v.y); }
            if (w2) { unsigned int o = wbase + t0 + t1 + __popc(m2 & lt);      if (o < WSEG) wseg[wid][o] = f2k(v.z); }
            if (w3) { unsigned int o = wbase + t0 + t1 + t2 + __popc(m3 & lt); if (o < WSEG) wseg[wid][o] = f2k(v.w); }
            wbase += tot;
        }
    }
    if (lane == 0) wc[wid] = wbase;
    __syncthreads();

    if (tid == 0) {
        unsigned int t = 0; int ov = 0;
        #pragma unroll
        for (int w = 0; w < GWARPS; w++) {
            if (wc[w] > WSEG) ov = 1;
            pre[w] = t;
            t += wc[w];
        }
        if (t > CSEG) ov = 1;
        s_tot = ov ? 0xFFFFFFFFu : t;
        g_ccnt[row][chk] = s_tot;
    }
    __syncthreads();

    if (s_tot != 0xFFFFFFFFu) {
        unsigned int n = wc[wid];
        unsigned int* dst = &g_buf[row][chk * CSEG + pre[wid]];
        for (unsigned int i = lane; i < n; i += 32) dst[i] = wseg[wid][i];
    }
}

// ===================== Kernel 2: per-row selection =====================
extern __shared__ unsigned int smem_u[];

__global__ __launch_bounds__(NTHREADS, 1)
void select_kernel(const float* __restrict__ x,
                   const float* __restrict__ alpha_p,
                   const float* __restrict__ beta_p)
{
    unsigned int* hist = smem_u;             // NBINS
    unsigned int* aux  = hist + NBINS;       // NTHREADS
    unsigned int* mix  = aux + NTHREADS;     // MCAP
    unsigned int* sbuf = mix + MCAP;         // SCAP

    __shared__ unsigned int cpre[CHUNKS + 1];
    __shared__ unsigned int s_M, scnt;
    __shared__ int          s_bad;
    __shared__ int          binOf[4];
    __shared__ unsigned int preOf[4];
    __shared__ float        s_v[4];

    const int tid = threadIdx.x;
    const int row = blockIdx.x;
    const float4* xr = (const float4*)(x + (size_t)row * NPERROW);

    const unsigned int BL2 = f2k(-2.0f) >> 18;   // bin containing -2.0 (max of bin)
    const unsigned int BH2 = f2k( 2.0f) >> 18;   // bin containing +2.0 (min of bin)

    if (tid == 0) {
        unsigned int t = 0; int bad = 0;
        #pragma unroll
        for (int c = 0; c < CHUNKS; c++) {
            unsigned int cc = g_ccnt[row][c];
            if (cc > CSEG) { bad = 1; cc = 0; }
            cpre[c] = t;
            t += cc;
        }
        cpre[CHUNKS] = t;
        if (t < 5246u) bad = 1;   // need >=2623 in each tail minimum
        s_M = t; s_bad = bad;
    }
    __syncthreads();

    const unsigned int M = s_M;
    int mode = s_bad ? 1 : 0;     // 0 = fast (tail set), 1 = exact full fallback

    if (mode == 0) {
        // load chunk segments contiguously into mix[] (each cnt <= 1024 = NTHREADS)
        #pragma unroll
        for (int c = 0; c < CHUNKS; c++) {
            unsigned int cnt = cpre[c + 1] - cpre[c];
            if ((unsigned int)tid < cnt) mix[cpre[c] + tid] = g_buf[row][c * CSEG + tid];
        }
    }
    __syncthreads();

    unsigned int RANKS[4];
    unsigned int TOT;

    for (;;) {
        #pragma unroll
        for (int j = 0; j < BPT; j++) hist[tid + j * NTHREADS] = 0u;
        __syncthreads();

        if (mode == 0) {
            TOT = M;
            RANKS[0] = 2621u; RANKS[1] = 2622u; RANKS[2] = M - 2623u; RANKS[3] = M - 2622u;
            for (unsigned int i = tid; i < M; i += NTHREADS)
                atomicAdd(&hist[mix[i] >> 18], 1u);
        } else {
            TOT = (unsigned int)NPERROW;
            RANKS[0] = 2621u; RANKS[1] = 2622u; RANKS[2] = 259521u; RANKS[3] = 259522u;
            for (int i = tid; i < NV4; i += NTHREADS) {
                float4 v = xr[i];
                atomicAdd(&hist[f2k(v.x) >> 18], 1u);
                atomicAdd(&hist[f2k(v.y) >> 18], 1u);
                atomicAdd(&hist[f2k(v.z) >> 18], 1u);
                atomicAdd(&hist[f2k(v.w) >> 18], 1u);
            }
        }
        __syncthreads();

        // exclusive prefix over hist
        {
            unsigned int loc[BPT];
            unsigned int s = 0;
            #pragma unroll
            for (int j = 0; j < BPT; j++) { loc[j] = hist[tid * BPT + j]; s += loc[j]; }
            aux[tid] = s;
            __syncthreads();
            for (int off = 1; off < NTHREADS; off <<= 1) {
                unsigned int v   = aux[tid];
                unsigned int add = (tid >= off) ? aux[tid - off] : 0u;
                __syncthreads();
                aux[tid] = v + add;
                __syncthreads();
            }
            unsigned int run = aux[tid] - s;
            #pragma unroll
            for (int j = 0; j < BPT; j++) {
                unsigned int c = loc[j];
                hist[tid * BPT + j] = run;
                run += c;
            }
        }
        __syncthreads();   // neighbors read hist[b+1] below

        #pragma unroll
        for (int j = 0; j < BPT; j++) {
            int b = tid * BPT + j;
            unsigned int p  = hist[b];
            unsigned int nx = (b == NBINS - 1) ? TOT : hist[b + 1];
            #pragma unroll
            for (int q = 0; q < 4; q++) {
                if (p <= RANKS[q] && RANKS[q] < nx) { binOf[q] = b; preOf[q] = p; }
            }
        }
        __syncthreads();

        if (mode == 0) {
            // ranks must lie strictly inside the gathered tails
            bool bad = (binOf[1] > (int)BL2) || (binOf[2] < (int)BH2);
            if (bad) { mode = 1; __syncthreads(); continue; }
        }
        break;
    }

    // ---- extract candidates per side, sort, pick order stats ----
    #pragma unroll
    for (int side = 0; side < 2; side++) {
        const int b0 = binOf[side * 2];
        const int b1 = binOf[side * 2 + 1];
        const unsigned int kmin = (unsigned int)b0 << 18;
        const unsigned int kmax = (((unsigned int)(b1 + 1)) << 18) - 1u;

        if (tid == 0) scnt = 0u;
        __syncthreads();

        if (mode == 0) {
            // padded bound -> uniform ballot trip counts
            unsigned int Mr = (M + NTHREADS - 1u) / NTHREADS * NTHREADS;
            for (unsigned int i = tid; i < Mr; i += NTHREADS) {
                bool inb = (i < M);
                unsigned int k = inb ? mix[i] : 0u;
                wpush(inb && k >= kmin && k <= kmax, k, &scnt, sbuf, SCAP);
            }
        } else {
            for (int i = tid; i < NV4; i += NTHREADS) {
                float4 v = xr[i];
                unsigned int ks[4] = {f2k(v.x), f2k(v.y), f2k(v.z), f2k(v.w)};
                #pragma unroll
                for (int e = 0; e < 4; e++)
                    wpush(ks[e] >= kmin && ks[e] <= kmax, ks[e], &scnt, sbuf, SCAP);
            }
        }
        __syncthreads();

        int m = (int)min(scnt, (unsigned int)SCAP);
        bitonic_sort(sbuf, m, tid);
        __syncthreads();

        if (tid == 0) {
            unsigned int r = RANKS[side * 2] - preOf[side * 2];
            if ((int)r > m - 2) r = (unsigned int)(m - 2);
            s_v[side * 2]     = k2f(sbuf[r]);
            s_v[side * 2 + 1] = k2f(sbuf[r + 1]);
        }
        __syncthreads();
    }

    if (tid == 0) {
        double posLo  = 0.01 * (double)(NPERROW - 1);
        double posHi  = 0.99 * (double)(NPERROW - 1);
        double fracLo = posLo - 2621.0;
        double fracHi = posHi - 259521.0;

        double i1  = (double)s_v[0] + fracLo * ((double)s_v[1] - (double)s_v[0]);
        double i99 = (double)s_v[2] + fracHi * ((double)s_v[3] - (double)s_v[2]);

        float alpha = alpha_p[0];
        float beta  = beta_p[0];
        float th = (float)(i1 + (i99 - i1) * (double)alpha);
        float mask   = (th > 1e-14f) ? 1.0f : 0.0f;
        float th_new = th * mask + (1.0f - mask);
        g_scale[row] = beta / th_new;
        g_t[row]     = th * mask;
    }
}

// ===================== Kernel 3: streaming gate =====================
__global__ __launch_bounds__(GTH)
void gate_kernel(const float* __restrict__ x, float* __restrict__ out)
{
    const int c   = blockIdx.x;
    const int row = c >> 4;            // CHUNKS = 16
    const int chk = c & 15;
    const float4* xr   = (const float4*)(x   + (size_t)row * NPERROW) + (size_t)chk * V4C;
    float4*       outr = (float4*)      (out + (size_t)row * NPERROW) + (size_t)chk * V4C;

    const float scale = g_scale[row];
    const float t     = g_t[row];
    const float L2E   = 1.4426950408889634f;
    const float a = scale * L2E;        // exp(-(scale*(|x|-t))) = 2^(-a*|x| + b)
    const float b = scale * t * L2E;

    #pragma unroll 4
    for (int i = threadIdx.x; i < V4C; i += GTH) {
        float4 v = __ldcs(&xr[i]);
        float4 o;
        o.x = fmaxf(v.x, 0.0f) * rcpa(1.0f + ex2a(fmaf(fabsf(v.x), -a, b)));
        o.y = fmaxf(v.y, 0.0f) * rcpa(1.0f + ex2a(fmaf(fabsf(v.y), -a, b)));
        o.z = fmaxf(v.z, 0.0f) * rcpa(1.0f + ex2a(fmaf(fabsf(v.z), -a, b)));
        o.w = fmaxf(v.w, 0.0f) * rcpa(1.0f + ex2a(fmaf(fabsf(v.w), -a, b)));
        __stcs(&outr[i], o);
    }
}

extern "C" void kernel_launch(void* const* d_in, const int* in_sizes, int n_in,
                              void* d_out, int out_size)
{
    const float* x     = (const float*)d_in[0];
    const float* alpha = (const float*)d_in[1];
    const float* beta  = (const float*)d_in[2];
    float* out = (float*)d_out;

    cudaFuncSetAttribute(select_kernel, cudaFuncAttributeMaxDynamicSharedMemorySize, SMEM_BYTES);

    gather_kernel<<<NROWS * CHUNKS, GTH>>>(x);
    select_kernel<<<NROWS, NTHREADS, SMEM_BYTES>>>(x, alpha, beta);
    gate_kernel<<<NROWS * CHUNKS, GTH>>>(x, out);
}

// round 7
// speedup vs baseline: 2.0254x; 1.2005x over previous
#include <cuda_runtime.h>
#include <math.h>

#define NPERROW (512*512)            // 262144
#define NROWS   128
#define NV4     (NPERROW/4)          // 65536
#define FULLM   0xFFFFFFFFu

// ---- gather / gate shape ----
#define CHUNKS  16
#define GTH     256
#define V4C     (NV4/CHUNKS)         // 4096 float4 per chunk
#define V4T     (V4C/GTH)            // 16 float4 per thread
#define GWARPS  (GTH/32)             // 8
#define TCAP    24                   // per-thread stage cap (exp 2.9, ~11 sigma)
#define CSEG    1024                 // per-chunk global segment cap (exp ~746)

// ---- selection ----
#define NTHREADS 1024
#define NBINS   16384                // top-14-bit histogram (key bits [18,32))
#define BPT     (NBINS/NTHREADS)     // 16
#define MCAP    (CHUNKS*CSEG)        // 16384
#define SMEM_WORDS (NBINS + MCAP + 4096 + 1024)   // 37888
#define SMEM_BYTES (SMEM_WORDS*4)                 // 151552

__device__ unsigned int g_buf[NROWS][CHUNKS*CSEG];   // 8 MB scratch
__device__ unsigned int g_ccnt[NROWS][CHUNKS];       // per-chunk counts (0xFFFFFFFF = overflow)
__device__ float g_scale[NROWS];
__device__ float g_t[NROWS];

// monotone float -> uint key
__device__ __forceinline__ unsigned int f2k(float f) {
    unsigned int u = __float_as_uint(f);
    return u ^ ((unsigned int)((int)u >> 31) | 0x80000000u);
}
__device__ __forceinline__ float k2f(unsigned int k) {
    unsigned int u = (k & 0x80000000u) ? (k ^ 0x80000000u) : ~k;
    return __uint_as_float(u);
}
__device__ __forceinline__ float ex2a(float x){ float r; asm("ex2.approx.ftz.f32 %0, %1;" : "=f"(r) : "f"(x)); return r; }
__device__ __forceinline__ float rcpa(float x){ float r; asm("rcp.approx.ftz.f32 %0, %1;" : "=f"(r) : "f"(x)); return r; }

// ===================== Kernel 1: wide tail gather =====================
__global__ __launch_bounds__(GTH)
void gather_kernel(const float* __restrict__ x)
{
    __shared__ unsigned int stage[TCAP * GTH];   // per-thread stripes, conflict-free
    __shared__ unsigned int wsum[GWARPS];
    __shared__ int s_ov;

    const int tid  = threadIdx.x;
    const int lane = tid & 31;
    const int wid  = tid >> 5;
    const int row  = blockIdx.x >> 4;
    const int chk  = blockIdx.x & (CHUNKS - 1);
    const float4* xr = (const float4*)(x + (size_t)row * NPERROW) + (size_t)chk * V4C;

    if (tid == 0) s_ov = 0;
    __syncthreads();

    unsigned int cnt = 0;
    #pragma unroll 4
    for (int it = 0; it < V4T; it++) {
        float4 v = __ldcs(&xr[tid + it * GTH]);
        if (fabsf(v.x) > 2.0f) { if (cnt < TCAP) stage[cnt * GTH + tid] = f2k(v.x); cnt++; }
        if (fabsf(v.y) > 2.0f) { if (cnt < TCAP) stage[cnt * GTH + tid] = f2k(v.y); cnt++; }
        if (fabsf(v.z) > 2.0f) { if (cnt < TCAP) stage[cnt * GTH + tid] = f2k(v.z); cnt++; }
        if (fabsf(v.w) > 2.0f) { if (cnt < TCAP) stage[cnt * GTH + tid] = f2k(v.w); cnt++; }
    }
    if (cnt > TCAP) s_ov = 1;   // benign race; ordered by the barriers below

    // block exclusive scan of per-thread counts (shfl-based)
    unsigned int inc = cnt;
    #pragma unroll
    for (int o = 1; o < 32; o <<= 1) {
        unsigned int t = __shfl_up_sync(FULLM, inc, o);
        if (lane >= o) inc += t;
    }
    if (lane == 31) wsum[wid] = inc;
    __syncthreads();
    if (tid < GWARPS) {
        unsigned int w = wsum[tid];
        #pragma unroll
        for (int o = 1; o < GWARPS; o <<= 1) {
            unsigned int t = __shfl_up_sync(0xFFu, w, o);
            if (tid >= o) w += t;
        }
        wsum[tid] = w;
    }
    __syncthreads();

    unsigned int pre   = (wid ? wsum[wid - 1] : 0u) + inc - cnt;
    unsigned int total = wsum[GWARPS - 1];
    int ov = s_ov || (total > CSEG);

    if (!ov) {
        unsigned int* dst = &g_buf[row][chk * CSEG + pre];
        for (unsigned int j = 0; j < cnt; j++) dst[j] = stage[j * GTH + tid];
    }
    if (tid == 0) g_ccnt[row][chk] = ov ? 0xFFFFFFFFu : total;
}

// ===================== Kernel 2: per-row selection (histogram radix-select) =====================
extern __shared__ unsigned int smem_u[];

// block-wide: exclusive-scan bank h[0..n), locate slot s with pre <= lr < pre+h[s].
// n <= NTHREADS. All threads must call. slot/pre are shared.
__device__ __forceinline__ void scan_locate(unsigned int* h, int n, unsigned int lr,
                                            int* slot, unsigned int* pre,
                                            unsigned int* wsum,
                                            int tid, int lane, int wid)
{
    unsigned int c = (tid < n) ? h[tid] : 0u;
    unsigned int inc = c;
    #pragma unroll
    for (int o = 1; o < 32; o <<= 1) {
        unsigned int t = __shfl_up_sync(FULLM, inc, o);
        if (lane >= o) inc += t;
    }
    if (lane == 31) wsum[wid] = inc;
    __syncthreads();
    if (tid < 32) {
        unsigned int w = wsum[tid];
        #pragma unroll
        for (int o = 1; o < 32; o <<= 1) {
            unsigned int t = __shfl_up_sync(FULLM, w, o);
            if (lane >= o) w += t;
        }
        wsum[tid] = w;
    }
    __syncthreads();
    unsigned int p = (wid ? wsum[wid - 1] : 0u) + inc - c;
    if (tid < n && lr >= p && lr < p + c) { *slot = tid; *pre = p; }
    __syncthreads();
}

__global__ __launch_bounds__(NTHREADS, 1)
void select_kernel(const float* __restrict__ x,
                   const float* __restrict__ alpha_p,
                   const float* __restrict__ beta_p)
{
    unsigned int* hist = smem_u;           // NBINS  (16384)
    unsigned int* mix  = hist + NBINS;     // MCAP   (16384)
    unsigned int* h2   = mix + MCAP;       // 4096 (4 banks x 1024)
    unsigned int* h3   = h2 + 4096;        // 1024 (4 banks x 256)

    __shared__ unsigned int wsum[32];
    __shared__ unsigned int cpre[CHUNKS + 1];
    __shared__ unsigned int s_M;
    __shared__ int          s_bad;
    __shared__ int          binOf[4];
    __shared__ unsigned int preOf[4];
    __shared__ int          slot2[4];
    __shared__ unsigned int pre2[4];
    __shared__ int          slot3[4];
    __shared__ unsigned int pre3[4];

    const int tid  = threadIdx.x;
    const int lane = tid & 31;
    const int wid  = tid >> 5;
    const int row  = blockIdx.x;
    const float4* xr = (const float4*)(x + (size_t)row * NPERROW);

    if (tid == 0) {
        unsigned int t = 0; int bad = 0;
        #pragma unroll
        for (int c = 0; c < CHUNKS; c++) {
            unsigned int cc = g_ccnt[row][c];
            if (cc > CSEG) { bad = 1; cc = 0; }
            cpre[c] = t;
            t += cc;
        }
        cpre[CHUNKS] = t;
        if (t < 5246u) bad = 1;   // both tails need >= 2623 elements
        s_M = t; s_bad = bad;
    }
    __syncthreads();

    const unsigned int M = s_M;
    int mode = s_bad ? 1 : 0;   // 0 = gathered tail set, 1 = exact full-row fallback

    if (mode == 0) {
        #pragma unroll
        for (int c = 0; c < CHUNKS; c++) {
            unsigned int cnt = cpre[c + 1] - cpre[c];   // <= CSEG = NTHREADS
            if ((unsigned int)tid < cnt) mix[cpre[c] + tid] = g_buf[row][c * CSEG + tid];
        }
    }
    __syncthreads();

    const unsigned int BL2 = f2k(-2.0f) >> 18;
    const unsigned int BH2 = f2k( 2.0f) >> 18;
    unsigned int R[4];

    // ---------------- L1: 14-bit histogram + inline locate ----------------
    for (;;) {
        if (mode == 0) { R[0] = 2621u; R[1] = 2622u; R[2] = M - 2623u; R[3] = M - 2622u; }
        else           { R[0] = 2621u; R[1] = 2622u; R[2] = 259521u;   R[3] = 259522u;  }

        #pragma unroll
        for (int j = 0; j < BPT; j++) hist[tid + j * NTHREADS] = 0u;
        __syncthreads();

        if (mode == 0) {
            for (unsigned int i = tid; i < M; i += NTHREADS)
                atomicAdd(&hist[mix[i] >> 18], 1u);
        } else {
            for (int i = tid; i < NV4; i += NTHREADS) {
                float4 v = xr[i];
                atomicAdd(&hist[f2k(v.x) >> 18], 1u);
                atomicAdd(&hist[f2k(v.y) >> 18], 1u);
                atomicAdd(&hist[f2k(v.z) >> 18], 1u);
                atomicAdd(&hist[f2k(v.w) >> 18], 1u);
            }
        }
        __syncthreads();

        // shfl-based scan over 16384 bins + inline rank locate
        unsigned int loc[BPT];
        unsigned int s = 0;
        #pragma unroll
        for (int j = 0; j < BPT; j++) { loc[j] = hist[tid * BPT + j]; s += loc[j]; }
        unsigned int inc = s;
        #pragma unroll
        for (int o = 1; o < 32; o <<= 1) {
            unsigned int t = __shfl_up_sync(FULLM, inc, o);
            if (lane >= o) inc += t;
        }
        if (lane == 31) wsum[wid] = inc;
        __syncthreads();
        if (tid < 32) {
            unsigned int w = wsum[tid];
            #pragma unroll
            for (int o = 1; o < 32; o <<= 1) {
                unsigned int t = __shfl_up_sync(FULLM, w, o);
                if (lane >= o) w += t;
            }
            wsum[tid] = w;
        }
        __syncthreads();
        unsigned int run = (wid ? wsum[wid - 1] : 0u) + inc - s;
        #pragma unroll
        for (int j = 0; j < BPT; j++) {
            unsigned int c = loc[j];
            int b = tid * BPT + j;
            #pragma unroll
            for (int q = 0; q < 4; q++)
                if (run <= R[q] && R[q] < run + c) { binOf[q] = b; preOf[q] = run; }
            run += c;
        }
        __syncthreads();

        if (mode == 0) {
            // ranks must lie strictly inside the gathered tails
            if (binOf[1] > (int)BL2 || binOf[2] < (int)BH2) { mode = 1; __syncthreads(); continue; }
        }
        break;
    }

    // ---------------- L2: 4 banks x 1024 sub-bins (key bits [8,18)) ----------------
    for (int j = tid; j < 4096; j += NTHREADS) h2[j] = 0u;
    __syncthreads();
    if (mode == 0) {
        for (unsigned int i = tid; i < M; i += NTHREADS) {
            unsigned int k = mix[i];
            int b = (int)(k >> 18);
            unsigned int sub = (k >> 8) & 1023u;
            #pragma unroll
            for (int q = 0; q < 4; q++)
                if (b == binOf[q]) atomicAdd(&h2[q * 1024 + sub], 1u);
        }
    } else {
        for (int i = tid; i < NV4; i += NTHREADS) {
            float4 v = xr[i];
            unsigned int ks[4] = {f2k(v.x), f2k(v.y), f2k(v.z), f2k(v.w)};
            #pragma unroll
            for (int e = 0; e < 4; e++) {
                unsigned int k = ks[e];
                int b = (int)(k >> 18);
                unsigned int sub = (k >> 8) & 1023u;
                #pragma unroll
                for (int q = 0; q < 4; q++)
                    if (b == binOf[q]) atomicAdd(&h2[q * 1024 + sub], 1u);
            }
        }
    }
    __syncthreads();
    #pragma unroll
    for (int q = 0; q < 4; q++)
        scan_locate(h2 + q * 1024, 1024, R[q] - preOf[q], &slot2[q], &pre2[q], wsum, tid, lane, wid);

    // ---------------- L3: 4 banks x 256 (key bits [0,8)) -> exact key ----------------
    unsigned int tgt24[4];
    #pragma unroll
    for (int q = 0; q < 4; q++) tgt24[q] = ((unsigned int)binOf[q] << 10) | (unsigned int)slot2[q];

    for (int j = tid; j < 1024; j += NTHREADS) h3[j] = 0u;
    __syncthreads();
    if (mode == 0) {
        for (unsigned int i = tid; i < M; i += NTHREADS) {
            unsigned int k = mix[i];
            unsigned int p24 = k >> 8;
            #pragma unroll
            for (int q = 0; q < 4; q++)
                if (p24 == tgt24[q]) atomicAdd(&h3[q * 256 + (k & 255u)], 1u);
        }
    } else {
        for (int i = tid; i < NV4; i += NTHREADS) {
            float4 v = xr[i];
            unsigned int ks[4] = {f2k(v.x), f2k(v.y), f2k(v.z), f2k(v.w)};
            #pragma unroll
            for (int e = 0; e < 4; e++) {
                unsigned int k = ks[e];
                unsigned int p24 = k >> 8;
                #pragma unroll
                for (int q = 0; q < 4; q++)
                    if (p24 == tgt24[q]) atomicAdd(&h3[q * 256 + (k & 255u)], 1u);
            }
        }
    }
    __syncthreads();
    #pragma unroll
    for (int q = 0; q < 4; q++)
        scan_locate(h3 + q * 256, 256, R[q] - preOf[q] - pre2[q], &slot3[q], &pre3[q], wsum, tid, lane, wid);

    // ---------------- threshold ----------------
    if (tid == 0) {
        float v[4];
        #pragma unroll
        for (int q = 0; q < 4; q++)
            v[q] = k2f((tgt24[q] << 8) | (unsigned int)slot3[q]);

        double posLo  = 0.01 * (double)(NPERROW - 1);
        double posHi  = 0.99 * (double)(NPERROW - 1);
        double fracLo = posLo - 2621.0;
        double fracHi = posHi - 259521.0;

        double i1  = (double)v[0] + fracLo * ((double)v[1] - (double)v[0]);
        double i99 = (double)v[2] + fracHi * ((double)v[3] - (double)v[2]);

        float alpha = alpha_p[0];
        float beta  = beta_p[0];
        float th = (float)(i1 + (i99 - i1) * (double)alpha);
        float mask   = (th > 1e-14f) ? 1.0f : 0.0f;
        float th_new = th * mask + (1.0f - mask);
        g_scale[row] = beta / th_new;
        g_t[row]     = th * mask;
    }
}

// ===================== Kernel 3: streaming gate =====================
__global__ __launch_bounds__(GTH)
void gate_kernel(const float* __restrict__ x, float* __restrict__ out)
{
    const int c   = blockIdx.x;
    const int row = c >> 4;            // CHUNKS = 16
    const int chk = c & 15;
    const float4* xr   = (const float4*)(x   + (size_t)row * NPERROW) + (size_t)chk * V4C;
    float4*       outr = (float4*)      (out + (size_t)row * NPERROW) + (size_t)chk * V4C;

    const float scale = g_scale[row];
    const float t     = g_t[row];
    const float L2E   = 1.4426950408889634f;
    const float a = scale * L2E;        // exp(-(scale*(|x|-t))) = 2^(-a*|x| + b)
    const float b = scale * t * L2E;

    #pragma unroll 4
    for (int i = threadIdx.x; i < V4C; i += GTH) {
        float4 v = __ldcs(&xr[i]);
        float4 o;
        o.x = fmaxf(v.x, 0.0f) * rcpa(1.0f + ex2a(fmaf(fabsf(v.x), -a, b)));
        o.y = fmaxf(v.y, 0.0f) * rcpa(1.0f + ex2a(fmaf(fabsf(v.y), -a, b)));
        o.z = fmaxf(v.z, 0.0f) * rcpa(1.0f + ex2a(fmaf(fabsf(v.z), -a, b)));
        o.w = fmaxf(v.w, 0.0f) * rcpa(1.0f + ex2a(fmaf(fabsf(v.w), -a, b)));
        __stcs(&outr[i], o);
    }
}

extern "C" void kernel_launch(void* const* d_in, const int* in_sizes, int n_in,
                              void* d_out, int out_size)
{
    const float* x     = (const float*)d_in[0];
    const float* alpha = (const float*)d_in[1];
    const float* beta  = (const float*)d_in[2];
    float* out = (float*)d_out;

    cudaFuncSetAttribute(select_kernel, cudaFuncAttributeMaxDynamicSharedMemorySize, SMEM_BYTES);

    gather_kernel<<<NROWS * CHUNKS, GTH>>>(x);
    select_kernel<<<NROWS, NTHREADS, SMEM_BYTES>>>(x, alpha, beta);
    gate_kernel<<<NROWS * CHUNKS, GTH>>>(x, out);
}